// round 5
// baseline (speedup 1.0000x reference)
#include <cuda_runtime.h>

// ---------------------------------------------------------------------------
// C3 sparsely-connected 5x5 conv, fp32, packed f32x2 FFMA path (sm_103a).
// x: [32,6,512,512], w: [16,6,5,5], bias: [16] -> out: [32,16,508,508]
//
// Block: one batch, 64x16 output tile, all 16 output channels.
// Thread: 4 consecutive output pixels x 16 channels, accumulated in
//         packed f32x2 registers via fma.rn.f32x2 (2 MACs/issue).
// Smem: input tile 6x20x68 f32 (32640 B) + all weights duplicated as
//       (w,w) u64 pairs (19200 B) -> 51840 B dynamic smem, 2 CTAs/SM.
// Connectivity is compile-time unrolled (ci -> its 10 connected co's),
// so unconnected weights are simply never touched (== masking).
// ---------------------------------------------------------------------------

#define IN_H 512
#define IN_W 512
#define OUT_H 508
#define OUT_W 508
#define N_CI 6
#define N_CO 16

#define TILE_W 64
#define TILE_H 16
#define IN_TW 68   // TILE_W + 4
#define IN_TH 20   // TILE_H + 4
#define NTHREADS 256

#define SW_BYTES   (N_CO * N_CI * 25 * 8)            // 19200
#define SIN_FLOATS (N_CI * IN_TH * IN_TW)            // 8160
#define SMEM_BYTES (SW_BYTES + SIN_FLOATS * 4)       // 51840

// ci -> list of 10 connected output channels (inverse of MAP_S2)
__device__ constexpr int CI2CO[6][10] = {
    {0, 4, 5, 6, 9, 10, 11, 12, 14, 15},   // ci 0
    {0, 1, 5, 6, 7, 10, 11, 12, 13, 15},   // ci 1
    {0, 1, 2, 6, 7, 8, 11, 13, 14, 15},    // ci 2
    {1, 2, 3, 6, 7, 8, 9, 12, 14, 15},     // ci 3
    {2, 3, 4, 7, 8, 9, 10, 12, 13, 15},    // ci 4
    {3, 4, 5, 8, 9, 10, 11, 13, 14, 15},   // ci 5
};

__device__ __forceinline__ unsigned long long pk2(float lo, float hi) {
    unsigned long long r;
    asm("mov.b64 %0, {%1, %2};" : "=l"(r) : "f"(lo), "f"(hi));
    return r;
}

__device__ __forceinline__ void fma2(unsigned long long& d,
                                     unsigned long long a,
                                     unsigned long long b) {
    // d = a * b + d, elementwise on the two packed f32 lanes
    asm("fma.rn.f32x2 %0, %1, %2, %0;" : "+l"(d) : "l"(a), "l"(b));
}

__device__ __forceinline__ float2 upk(unsigned long long v) {
    float2 r;
    asm("mov.b64 {%0, %1}, %2;" : "=f"(r.x), "=f"(r.y) : "l"(v));
    return r;
}

__global__ __launch_bounds__(NTHREADS, 2)
void c3_kernel(const float* __restrict__ x,
               const float* __restrict__ w,
               const float* __restrict__ bias,
               float* __restrict__ out) {
    extern __shared__ unsigned char smem[];
    unsigned long long* sW = reinterpret_cast<unsigned long long*>(smem);       // 2400 pairs
    float* sIn = reinterpret_cast<float*>(smem + SW_BYTES);                     // 8160 floats

    const int tid = threadIdx.x;
    const int b   = blockIdx.z;
    const int x0  = blockIdx.x * TILE_W;
    const int y0  = blockIdx.y * TILE_H;

    // --- stage weights: duplicate each scalar into a (w,w) 64-bit pair ------
    for (int i = tid; i < N_CO * N_CI * 25; i += NTHREADS) {
        float wv = w[i];
        sW[i] = pk2(wv, wv);
    }

    // --- stage input tile: 6 x 20 x 68, zero-padded past image edge --------
    // 17 float4 per row, 20 rows, 6 channels = 2040 float4 total.
    const float* xb = x + (size_t)b * (N_CI * IN_H * IN_W);
    for (int i = tid; i < N_CI * IN_TH * 17; i += NTHREADS) {
        int ci  = i / (IN_TH * 17);
        int rem = i - ci * (IN_TH * 17);
        int r   = rem / 17;
        int c4  = (rem - r * 17) * 4;
        int gy  = y0 + r;
        int gx  = x0 + c4;
        float4 v = make_float4(0.f, 0.f, 0.f, 0.f);
        if (gy < IN_H && gx < IN_W) {
            v = *reinterpret_cast<const float4*>(
                    xb + (size_t)ci * (IN_H * IN_W) + (size_t)gy * IN_W + gx);
        }
        *reinterpret_cast<float4*>(sIn + ci * (IN_TH * IN_TW) + r * IN_TW + c4) = v;
    }
    __syncthreads();

    const int txi = (tid & 15) * 4;   // thread's x offset in tile (4 px wide)
    const int tyi = tid >> 4;         // thread's y row in tile

    // --- accumulators: 16 channels x 2 packed pairs, init with bias --------
    unsigned long long acc[N_CO][2];
#pragma unroll
    for (int co = 0; co < N_CO; ++co) {
        float bv = __ldg(bias + co);
        acc[co][0] = pk2(bv, bv);
        acc[co][1] = acc[co][0];
    }

#pragma unroll
    for (int ci = 0; ci < N_CI; ++ci) {
        const float* base = sIn + ci * (IN_TH * IN_TW) + tyi * IN_TW + txi;
#pragma unroll 1
        for (int ky = 0; ky < 5; ++ky) {
            float4 a = *reinterpret_cast<const float4*>(base + ky * IN_TW);
            float4 c = *reinterpret_cast<const float4*>(base + ky * IN_TW + 4);
            // shifted packed pairs p[j] = (in[j], in[j+1]), j = 0..6
            unsigned long long p[7];
            p[0] = pk2(a.x, a.y);
            p[1] = pk2(a.y, a.z);
            p[2] = pk2(a.z, a.w);
            p[3] = pk2(a.w, c.x);
            p[4] = pk2(c.x, c.y);
            p[5] = pk2(c.y, c.z);
            p[6] = pk2(c.z, c.w);
            const unsigned long long* wrow = sW + ci * 25 + ky * 5;
#pragma unroll
            for (int kx = 0; kx < 5; ++kx) {
#pragma unroll
                for (int t = 0; t < 10; ++t) {
                    const int co = CI2CO[ci][t];
                    unsigned long long wv = wrow[co * (N_CI * 25) + kx];
                    fma2(acc[co][0], p[kx], wv);       // pixels 0,1
                    fma2(acc[co][1], p[kx + 2], wv);   // pixels 2,3
                }
            }
        }
    }

    // --- store: float4 per channel, guarded at right/bottom edges ----------
    const int ox = x0 + txi;
    const int oy = y0 + tyi;
    if (ox < OUT_W && oy < OUT_H) {
        float* ob = out + (size_t)b * (N_CO * OUT_H * OUT_W)
                        + (size_t)oy * OUT_W + ox;
#pragma unroll
        for (int co = 0; co < N_CO; ++co) {
            float2 v0 = upk(acc[co][0]);
            float2 v1 = upk(acc[co][1]);
            *reinterpret_cast<float4*>(ob + (size_t)co * (OUT_H * OUT_W)) =
                make_float4(v0.x, v0.y, v1.x, v1.y);
        }
    }
}

extern "C" void kernel_launch(void* const* d_in, const int* in_sizes, int n_in,
                              void* d_out, int out_size) {
    const float* x    = (const float*)d_in[0];   // [32,6,512,512]
    const float* w    = (const float*)d_in[1];   // [16,6,5,5]
    const float* bias = (const float*)d_in[2];   // [16]
    float* out = (float*)d_out;                  // [32,16,508,508]

    cudaFuncSetAttribute(c3_kernel,
                         cudaFuncAttributeMaxDynamicSharedMemorySize,
                         SMEM_BYTES);

    dim3 grid((OUT_W + TILE_W - 1) / TILE_W,    // 8
              (OUT_H + TILE_H - 1) / TILE_H,    // 32
              32);                              // batch
    c3_kernel<<<grid, NTHREADS, SMEM_BYTES>>>(x, w, bias, out);
}

// round 7
// speedup vs baseline: 1.0214x; 1.0214x over previous
#include <cuda_runtime.h>

// ---------------------------------------------------------------------------
// C3 sparsely-connected 5x5 conv, fp32, FFMA2 (fma.rn.f32x2) path, sm_103a.
// x: [32,6,512,512], w: [16,6,5,5], bias: [16] -> out: [32,16,508,508]
//
// R7 = R6 design with the device-constexpr fix:
//  - Block: one batch, 64x16 output tile. 256 threads.
//  - Thread: 8 consecutive output px (4 packed f32x2 pairs) x 8 output chans.
//    The 16 channels are split into two balanced halves across tid bit 7.
//  - Weight smem pairs (w,w): each LDS.64 weight feeds 4 FFMA2.
//  - Input tile stored TWICE in smem (aligned + shifted-by-1-float) so every
//    shifted pair (in[j], in[j+1]) is a direct aligned LDS.64 -> no pack MOVs.
//  - Row stride 70 floats => warp's input LDS.64 covers all 16 8B bank-groups
//    exactly twice (2-phase minimum, conflict-free).
// ---------------------------------------------------------------------------

#define IN_H 512
#define IN_W 512
#define OUT_H 508
#define OUT_W 508
#define N_CI 6
#define N_CO 16

#define TILE_W 64
#define TILE_H 16
#define IN_TW 68          // TILE_W + 4 valid floats
#define IN_TH 20          // TILE_H + 4
#define SA_STRIDE 70      // padded row stride (floats)
#define CI_TILE (IN_TH * SA_STRIDE)   // 1400 floats per channel
#define NTHREADS 256

#define SW_PAIRS (N_CO * N_CI * 25)              // 2400
#define SW_BYTES (SW_PAIRS * 8)                  // 19200
#define SA_BYTES (N_CI * CI_TILE * 4)            // 33600
#define SMEM_BYTES (SW_BYTES + 2 * SA_BYTES)     // 86400

typedef unsigned long long u64;

// Balanced co partition: 30 connected (co,ci) pairs per half.
__device__ constexpr int H_CO[2][8] = {
    {0, 1, 2, 3, 6, 7, 8, 15},
    {4, 5, 9, 10, 11, 12, 13, 14},
};
// Per half, per ci: how many of this half's co are connected to ci,
// and their indices into H_CO[half].
__device__ constexpr int HCNT[2][6] = { {3, 5, 7, 7, 5, 3}, {7, 5, 3, 3, 5, 7} };
__device__ constexpr int HLST[2][6][7] = {
  { // half 0
    {0, 4, 7, 0, 0, 0, 0},        // ci0: co {0,6,15}
    {0, 1, 4, 5, 7, 0, 0},        // ci1: co {0,1,6,7,15}
    {0, 1, 2, 4, 5, 6, 7},        // ci2: co {0,1,2,6,7,8,15}
    {1, 2, 3, 4, 5, 6, 7},        // ci3: co {1,2,3,6,7,8,15}
    {2, 3, 5, 6, 7, 0, 0},        // ci4: co {2,3,7,8,15}
    {3, 6, 7, 0, 0, 0, 0},        // ci5: co {3,8,15}
  },
  { // half 1
    {0, 1, 2, 3, 4, 5, 7},        // ci0: co {4,5,9,10,11,12,14}
    {1, 3, 4, 5, 6, 0, 0},        // ci1: co {5,10,11,12,13}
    {4, 6, 7, 0, 0, 0, 0},        // ci2: co {11,13,14}
    {2, 5, 7, 0, 0, 0, 0},        // ci3: co {9,12,14}
    {0, 2, 3, 5, 6, 0, 0},        // ci4: co {4,9,10,12,13}
    {0, 1, 2, 3, 4, 6, 7},        // ci5: co {4,5,9,10,11,13,14}
  },
};

__device__ __forceinline__ u64 pk2(float lo, float hi) {
    u64 r;
    asm("mov.b64 %0, {%1, %2};" : "=l"(r) : "f"(lo), "f"(hi));
    return r;
}

__device__ __forceinline__ void fma2(u64& d, u64 a, u64 b) {
    asm("fma.rn.f32x2 %0, %1, %2, %0;" : "+l"(d) : "l"(a), "l"(b));
}

__device__ __forceinline__ float2 upk(u64 v) {
    float2 r;
    asm("mov.b64 {%0, %1}, %2;" : "=f"(r.x), "=f"(r.y) : "l"(v));
    return r;
}

template <int H>
__device__ __forceinline__ void compute_half(
    const float* __restrict__ sA, const float* __restrict__ sB,
    const u64* __restrict__ sW, const float* __restrict__ bias,
    float* __restrict__ out, int b, int x0, int y0, int txi, int row)
{
    // 8 channels x 4 packed pairs (8 px), init with bias
    u64 acc[8][4];
#pragma unroll
    for (int a = 0; a < 8; ++a) {
        float bv = __ldg(bias + H_CO[H][a]);
        u64 bb = pk2(bv, bv);
        acc[a][0] = bb; acc[a][1] = bb; acc[a][2] = bb; acc[a][3] = bb;
    }

#pragma unroll
    for (int ci = 0; ci < N_CI; ++ci) {
        const float* bA = sA + ci * CI_TILE + row * SA_STRIDE + txi;
        const float* bB = sB + ci * CI_TILE + row * SA_STRIDE + txi;
#pragma unroll 1
        for (int ky = 0; ky < 5; ++ky) {
            // pairs at even float offsets (0,2,..,10) from aligned copy,
            // odd offsets (1,3,..,9) from shifted copy — all aligned LDS.64
            u64 pe[6], po[5];
#pragma unroll
            for (int k = 0; k < 6; ++k)
                pe[k] = *reinterpret_cast<const u64*>(bA + ky * SA_STRIDE + 2 * k);
#pragma unroll
            for (int k = 0; k < 5; ++k)
                po[k] = *reinterpret_cast<const u64*>(bB + ky * SA_STRIDE + 2 * k);

            const u64* wk = sW + ci * 25 + ky * 5;
#pragma unroll
            for (int kx = 0; kx < 5; ++kx) {
#pragma unroll
                for (int t = 0; t < HCNT[H][ci]; ++t) {
                    const int a = HLST[H][ci][t];
                    u64 wv = wk[H_CO[H][a] * (N_CI * 25) + kx];
                    if (kx & 1) {
                        const int k0 = (kx - 1) / 2;
                        fma2(acc[a][0], po[k0],     wv);
                        fma2(acc[a][1], po[k0 + 1], wv);
                        fma2(acc[a][2], po[k0 + 2], wv);
                        fma2(acc[a][3], po[k0 + 3], wv);
                    } else {
                        const int k0 = kx / 2;
                        fma2(acc[a][0], pe[k0],     wv);
                        fma2(acc[a][1], pe[k0 + 1], wv);
                        fma2(acc[a][2], pe[k0 + 2], wv);
                        fma2(acc[a][3], pe[k0 + 3], wv);
                    }
                }
            }
        }
    }

    // store: two float4 per channel; ox is a multiple of 8, OUT_W%4==0 so
    // each float4 is all-valid or all-invalid.
    const int ox = x0 + txi;
    const int oy = y0 + row;
    if (oy < OUT_H) {
        float* ob = out + (size_t)b * (N_CO * OUT_H * OUT_W)
                        + (size_t)oy * OUT_W + ox;
        const bool second = (ox + 8 <= OUT_W);
#pragma unroll
        for (int a = 0; a < 8; ++a) {
            float* p = ob + (size_t)H_CO[H][a] * (OUT_H * OUT_W);
            float2 v0 = upk(acc[a][0]);
            float2 v1 = upk(acc[a][1]);
            *reinterpret_cast<float4*>(p) = make_float4(v0.x, v0.y, v1.x, v1.y);
            if (second) {
                float2 v2 = upk(acc[a][2]);
                float2 v3 = upk(acc[a][3]);
                *reinterpret_cast<float4*>(p + 4) =
                    make_float4(v2.x, v2.y, v3.x, v3.y);
            }
        }
    }
}

__global__ __launch_bounds__(NTHREADS, 2)
void c3_kernel(const float* __restrict__ x,
               const float* __restrict__ w,
               const float* __restrict__ bias,
               float* __restrict__ out) {
    extern __shared__ unsigned char smem[];
    u64*   sW = reinterpret_cast<u64*>(smem);                       // 2400 pairs
    float* sA = reinterpret_cast<float*>(smem + SW_BYTES);          // aligned tile
    float* sB = reinterpret_cast<float*>(smem + SW_BYTES + SA_BYTES); // shifted

    const int tid = threadIdx.x;
    const int b   = blockIdx.z;
    const int x0  = blockIdx.x * TILE_W;
    const int y0  = blockIdx.y * TILE_H;

    // --- stage weights as (w,w) 64-bit pairs --------------------------------
    for (int i = tid; i < SW_PAIRS; i += NTHREADS) {
        float wv = w[i];
        sW[i] = pk2(wv, wv);
    }

    // --- stage input tile into BOTH copies (aligned + shifted by 1 float) --
    const float* xb = x + (size_t)b * (N_CI * IN_H * IN_W);
    for (int i = tid; i < N_CI * IN_TH * 17; i += NTHREADS) {
        int ci  = i / (IN_TH * 17);
        int rem = i - ci * (IN_TH * 17);
        int r   = rem / 17;
        int c4  = (rem - r * 17) * 4;
        int gy  = y0 + r;
        int gx  = x0 + c4;
        float4 v = make_float4(0.f, 0.f, 0.f, 0.f);
        if (gy < IN_H && gx < IN_W) {
            v = *reinterpret_cast<const float4*>(
                    xb + (size_t)ci * (IN_H * IN_W) + (size_t)gy * IN_W + gx);
        }
        float* dA = sA + ci * CI_TILE + r * SA_STRIDE + c4;
        // stride 70 floats => 8B-aligned rows; store as two float2
        *reinterpret_cast<float2*>(dA)     = make_float2(v.x, v.y);
        *reinterpret_cast<float2*>(dA + 2) = make_float2(v.z, v.w);
        // shifted copy: B[c] = in[c+1]
        float* dB = sB + ci * CI_TILE + r * SA_STRIDE + c4;
        if (c4 > 0) dB[-1] = v.x;
        dB[0] = v.y; dB[1] = v.z; dB[2] = v.w;
    }
    __syncthreads();

    const int xg  = tid & 7;          // 8 x-groups of 8 px
    const int row = (tid >> 3) & 15;  // 16 rows
    const int coh = tid >> 7;         // channel half (uniform per warp)
    const int txi = xg * 8;

    if (coh == 0)
        compute_half<0>(sA, sB, sW, bias, out, b, x0, y0, txi, row);
    else
        compute_half<1>(sA, sB, sW, bias, out, b, x0, y0, txi, row);
}

extern "C" void kernel_launch(void* const* d_in, const int* in_sizes, int n_in,
                              void* d_out, int out_size) {
    const float* x    = (const float*)d_in[0];   // [32,6,512,512]
    const float* w    = (const float*)d_in[1];   // [16,6,5,5]
    const float* bias = (const float*)d_in[2];   // [16]
    float* out = (float*)d_out;                  // [32,16,508,508]

    cudaFuncSetAttribute(c3_kernel,
                         cudaFuncAttributeMaxDynamicSharedMemorySize,
                         SMEM_BYTES);

    dim3 grid((OUT_W + TILE_W - 1) / TILE_W,    // 8
              (OUT_H + TILE_H - 1) / TILE_H,    // 32
              32);                              // batch
    c3_kernel<<<grid, NTHREADS, SMEM_BYTES>>>(x, w, bias, out);
}

// round 8
// speedup vs baseline: 1.0805x; 1.0579x over previous
#include <cuda_runtime.h>

// ---------------------------------------------------------------------------
// C3 sparsely-connected 5x5 conv, fp32, FFMA2 (fma.rn.f32x2) path, sm_103a.
// x: [32,6,512,512], w: [16,6,5,5], bias: [16] -> out: [32,16,508,508]
//
// R8: occupancy-first redesign.
//  - 3 CTAs/SM (launch_bounds(256,3)), 24 warps/SM: acc shrunk to 8co x 2
//    pairs (4 px) = 32 regs so the whole thread fits in 84 regs.
//  - Tile 64x8 per CTA, two balanced 8-channel halves across tid bit 7.
//  - Input stride 68 floats (272B = 16 mod 128): conflict-free LDS.128.
//  - Dual smem copies (aligned + shifted 1 float): all shifted pairs are
//    direct aligned LDS.64/128, zero pack MOVs.
//  - Weights padded to 6 pairs/row (48B): 3 uniform loads per (co,ci,ky).
// ---------------------------------------------------------------------------

#define IN_H 512
#define IN_W 512
#define OUT_H 508
#define OUT_W 508
#define N_CI 6
#define N_CO 16

#define TILE_W 64
#define TILE_H 8
#define IN_TH 12          // TILE_H + 4
#define SA_STRIDE 68      // row stride in floats (272B ≡ 16 mod 128)
#define CI_TILE (IN_TH * SA_STRIDE)   // 816 floats per channel plane
#define NTHREADS 256

// weights: rows of 6 pairs (kx 0..4 + pad), 16B aligned
#define SW_PAIRS (N_CO * N_CI * 5 * 6)           // 2880
#define SW_BYTES (SW_PAIRS * 8)                  // 23040
#define SA_BYTES (N_CI * CI_TILE * 4)            // 19584
#define SMEM_BYTES (SW_BYTES + 2 * SA_BYTES)     // 62208

typedef unsigned long long u64;

// Balanced co partition: 30 connected (co,ci) pairs per half.
__device__ constexpr int H_CO[2][8] = {
    {0, 1, 2, 3, 6, 7, 8, 15},
    {4, 5, 9, 10, 11, 12, 13, 14},
};
__device__ constexpr int HCNT[2][6] = { {3, 5, 7, 7, 5, 3}, {7, 5, 3, 3, 5, 7} };
__device__ constexpr int HLST[2][6][7] = {
  { // half 0
    {0, 4, 7, 0, 0, 0, 0},        // ci0: co {0,6,15}
    {0, 1, 4, 5, 7, 0, 0},        // ci1: co {0,1,6,7,15}
    {0, 1, 2, 4, 5, 6, 7},        // ci2: co {0,1,2,6,7,8,15}
    {1, 2, 3, 4, 5, 6, 7},        // ci3: co {1,2,3,6,7,8,15}
    {2, 3, 5, 6, 7, 0, 0},        // ci4: co {2,3,7,8,15}
    {3, 6, 7, 0, 0, 0, 0},        // ci5: co {3,8,15}
  },
  { // half 1
    {0, 1, 2, 3, 4, 5, 7},        // ci0: co {4,5,9,10,11,12,14}
    {1, 3, 4, 5, 6, 0, 0},        // ci1: co {5,10,11,12,13}
    {4, 6, 7, 0, 0, 0, 0},        // ci2: co {11,13,14}
    {2, 5, 7, 0, 0, 0, 0},        // ci3: co {9,12,14}
    {0, 2, 3, 5, 6, 0, 0},        // ci4: co {4,9,10,12,13}
    {0, 1, 2, 3, 4, 6, 7},        // ci5: co {4,5,9,10,11,13,14}
  },
};

__device__ __forceinline__ u64 pk2(float lo, float hi) {
    u64 r;
    asm("mov.b64 %0, {%1, %2};" : "=l"(r) : "f"(lo), "f"(hi));
    return r;
}

__device__ __forceinline__ void fma2(u64& d, u64 a, u64 b) {
    asm("fma.rn.f32x2 %0, %1, %2, %0;" : "+l"(d) : "l"(a), "l"(b));
}

__device__ __forceinline__ float2 upk(u64 v) {
    float2 r;
    asm("mov.b64 {%0, %1}, %2;" : "=f"(r.x), "=f"(r.y) : "l"(v));
    return r;
}

template <int H>
__device__ __forceinline__ void compute_half(
    const float* __restrict__ sA, const float* __restrict__ sB,
    const u64* __restrict__ sW, const float* __restrict__ bias,
    float* __restrict__ out, int b, int x0, int y0, int txi, int row)
{
    // 8 channels x 2 packed pairs (4 px), init with bias
    u64 acc[8][2];
#pragma unroll
    for (int a = 0; a < 8; ++a) {
        float bv = __ldg(bias + H_CO[H][a]);
        u64 bb = pk2(bv, bv);
        acc[a][0] = bb; acc[a][1] = bb;
    }

#pragma unroll
    for (int ci = 0; ci < N_CI; ++ci) {
        const float* bA = sA + ci * CI_TILE + row * SA_STRIDE + txi;
        const float* bB = sB + ci * CI_TILE + row * SA_STRIDE + txi;
#pragma unroll 1
        for (int ky = 0; ky < 5; ++ky) {
            // even pairs j=0,2,4,6 from aligned copy: 2x LDS.128
            ulonglong2 e0 = *reinterpret_cast<const ulonglong2*>(bA + ky * SA_STRIDE);
            ulonglong2 e1 = *reinterpret_cast<const ulonglong2*>(bA + ky * SA_STRIDE + 4);
            // odd pairs j=1,3 from shifted copy: LDS.128; j=5: LDS.64
            ulonglong2 o0 = *reinterpret_cast<const ulonglong2*>(bB + ky * SA_STRIDE);
            u64        o2 = *reinterpret_cast<const u64*>(bB + ky * SA_STRIDE + 4);
            u64 pe[4] = {e0.x, e0.y, e1.x, e1.y};   // j = 0,2,4,6
            u64 po[3] = {o0.x, o0.y, o2};           // j = 1,3,5

#pragma unroll
            for (int t = 0; t < HCNT[H][ci]; ++t) {
                const int a  = HLST[H][ci][t];
                const int co = H_CO[H][a];
                const u64* wr = sW + ((co * N_CI + ci) * 5 + ky) * 6;
                ulonglong2 w01 = *reinterpret_cast<const ulonglong2*>(wr);
                ulonglong2 w23 = *reinterpret_cast<const ulonglong2*>(wr + 2);
                u64        w4  = wr[4];
                // kx=0: j=0 (pe0), j=2 (pe1)
                fma2(acc[a][0], pe[0], w01.x);
                fma2(acc[a][1], pe[1], w01.x);
                // kx=1: j=1 (po0), j=3 (po1)
                fma2(acc[a][0], po[0], w01.y);
                fma2(acc[a][1], po[1], w01.y);
                // kx=2: j=2 (pe1), j=4 (pe2)
                fma2(acc[a][0], pe[1], w23.x);
                fma2(acc[a][1], pe[2], w23.x);
                // kx=3: j=3 (po1), j=5 (po2)
                fma2(acc[a][0], po[1], w23.y);
                fma2(acc[a][1], po[2], w23.y);
                // kx=4: j=4 (pe2), j=6 (pe3)
                fma2(acc[a][0], pe[2], w4);
                fma2(acc[a][1], pe[3], w4);
            }
        }
    }

    // store: one float4 per channel (4 px, 16B aligned)
    const int ox = x0 + txi;
    const int oy = y0 + row;
    if (ox < OUT_W && oy < OUT_H) {
        float* ob = out + (size_t)b * (N_CO * OUT_H * OUT_W)
                        + (size_t)oy * OUT_W + ox;
#pragma unroll
        for (int a = 0; a < 8; ++a) {
            float2 v0 = upk(acc[a][0]);
            float2 v1 = upk(acc[a][1]);
            *reinterpret_cast<float4*>(ob + (size_t)H_CO[H][a] * (OUT_H * OUT_W)) =
                make_float4(v0.x, v0.y, v1.x, v1.y);
        }
    }
}

__global__ __launch_bounds__(NTHREADS, 3)
void c3_kernel(const float* __restrict__ x,
               const float* __restrict__ w,
               const float* __restrict__ bias,
               float* __restrict__ out) {
    extern __shared__ unsigned char smem[];
    u64*   sW = reinterpret_cast<u64*>(smem);
    float* sA = reinterpret_cast<float*>(smem + SW_BYTES);
    float* sB = reinterpret_cast<float*>(smem + SW_BYTES + SA_BYTES);

    const int tid = threadIdx.x;
    const int b   = blockIdx.z;
    const int x0  = blockIdx.x * TILE_W;
    const int y0  = blockIdx.y * TILE_H;

    // --- stage weights as (w,w) pairs, rows padded to 6 (48B, 16B-aligned) --
    for (int i = tid; i < N_CO * N_CI * 25; i += NTHREADS) {
        int co = i / 150;
        int r1 = i - co * 150;          // ci*25 + ky*5 + kx
        int ci = r1 / 25;
        int r2 = r1 - ci * 25;
        int ky = r2 / 5;
        int kx = r2 - ky * 5;
        float wv = w[i];
        sW[((co * N_CI + ci) * 5 + ky) * 6 + kx] = pk2(wv, wv);
    }

    // --- stage input tile into BOTH copies (aligned + shifted by 1 float) --
    const float* xb = x + (size_t)b * (N_CI * IN_H * IN_W);
    for (int i = tid; i < N_CI * IN_TH * 17; i += NTHREADS) {
        int ci  = i / (IN_TH * 17);
        int rem = i - ci * (IN_TH * 17);
        int r   = rem / 17;
        int c4  = (rem - r * 17) * 4;
        int gy  = y0 + r;
        int gx  = x0 + c4;
        float4 v = make_float4(0.f, 0.f, 0.f, 0.f);
        if (gy < IN_H && gx < IN_W) {
            v = *reinterpret_cast<const float4*>(
                    xb + (size_t)ci * (IN_H * IN_W) + (size_t)gy * IN_W + gx);
        }
        // aligned copy: stride 68 floats = 272B, rows 16B aligned -> STS.128
        float* dA = sA + ci * CI_TILE + r * SA_STRIDE + c4;
        *reinterpret_cast<float4*>(dA) = v;
        // shifted copy: B[c] = in[c+1]
        float* dB = sB + ci * CI_TILE + r * SA_STRIDE + c4;
        if (c4 > 0) dB[-1] = v.x;
        dB[0] = v.y; dB[1] = v.z; dB[2] = v.w;
    }
    __syncthreads();

    const int xg   = tid & 15;         // 16 x-groups of 4 px
    const int row  = (tid >> 4) & 7;   // 8 rows
    const int half = tid >> 7;         // channel half (uniform per warp)
    const int txi  = xg * 4;

    if (half == 0)
        compute_half<0>(sA, sB, sW, bias, out, b, x0, y0, txi, row);
    else
        compute_half<1>(sA, sB, sW, bias, out, b, x0, y0, txi, row);
}

extern "C" void kernel_launch(void* const* d_in, const int* in_sizes, int n_in,
                              void* d_out, int out_size) {
    const float* x    = (const float*)d_in[0];   // [32,6,512,512]
    const float* w    = (const float*)d_in[1];   // [16,6,5,5]
    const float* bias = (const float*)d_in[2];   // [16]
    float* out = (float*)d_out;                  // [32,16,508,508]

    cudaFuncSetAttribute(c3_kernel,
                         cudaFuncAttributeMaxDynamicSharedMemorySize,
                         SMEM_BYTES);

    dim3 grid((OUT_W + TILE_W - 1) / TILE_W,    // 8
              (OUT_H + TILE_H - 1) / TILE_H,    // 64
              32);                              // batch
    c3_kernel<<<grid, NTHREADS, SMEM_BYTES>>>(x, w, bias, out);
}